// round 15
// baseline (speedup 1.0000x reference)
#include <cuda_runtime.h>

#define FULLMASK 0xffffffffu
constexpr int Bn = 2048;
constexpr int Sn = 2048;
constexpr int K  = 12;     // taps for E-FIR / G prefix
constexpr int KS = 8;      // sigma-feedback taps in scan
constexpr int LCH = 32;    // stored steps per chunk (64 chunks/row)
constexpr int WUP = 48;    // warm-up steps (t0 = 32c-48)
constexpr int NR  = 67;    // columns per chunk-major row
constexpr int BUF = 32 * NR;   // 2144 floats per data row
constexpr int SSTR = 17;
constexpr float LOG2E = 1.4426950408889634f;
constexpr float LN2   = 0.6931471805599453f;

__device__ float g_alpha[K];
__device__ float g_beta[K];                   // pre-scaled by LOG2E
__device__ float g_gam[K + 1];                // prefix sums incl fcb

// ============================================================
// Kernel A: coefficients (K=12). Triggers PDL dependents at entry.
// ============================================================
__global__ void __launch_bounds__(64) coef_kernel(
        const float* __restrict__ Wih, const float* __restrict__ Bih,
        const float* __restrict__ Whh, const float* __restrict__ Bhh,
        const float* __restrict__ Fcw, const float* __restrict__ Fcb) {
    cudaTriggerProgrammaticLaunchCompletion();

    __shared__ __align__(16) float Ws[64 * 64];
    __shared__ __align__(16) float P[K][64];
    __shared__ __align__(16) float pbuf[2][64];
    __shared__ float uvb[3][64];
    __shared__ float sg[K];
    const int j = threadIdx.x;

    #pragma unroll
    for (int m = 0; m < 16; ++m)
        reinterpret_cast<float4*>(Ws)[j + 64 * m] =
            reinterpret_cast<const float4*>(Whh)[j + 64 * m];
    uvb[0][j] = Wih[2 * j];
    uvb[1][j] = Wih[2 * j + 1];
    uvb[2][j] = Bih[j] + Bhh[j];
    {
        float f = Fcw[j];
        P[0][j] = f;
        pbuf[0][j] = f;
    }
    __syncthreads();

    float Wc[64];
    #pragma unroll
    for (int r = 0; r < 64; ++r) Wc[r] = Ws[r * 64 + j];

    #pragma unroll 1
    for (int k = 1; k < K; ++k) {
        const float4* pp = reinterpret_cast<const float4*>(pbuf[(k - 1) & 1]);
        float a0 = 0.f, a1 = 0.f, a2 = 0.f, a3 = 0.f;
        #pragma unroll
        for (int m = 0; m < 16; ++m) {
            float4 q = pp[m];
            a0 = fmaf(Wc[4 * m + 0], q.x, a0);
            a1 = fmaf(Wc[4 * m + 1], q.y, a1);
            a2 = fmaf(Wc[4 * m + 2], q.z, a2);
            a3 = fmaf(Wc[4 * m + 3], q.w, a3);
        }
        float np = (a0 + a1) + (a2 + a3);
        pbuf[k & 1][j] = np;
        P[k][j] = np;
        __syncthreads();
    }

    if (j < K) {
        const float* Pk = P[j];
        float A = 0.f, B = 0.f, C = 0.f;
        #pragma unroll 8
        for (int m = 0; m < 64; ++m) {
            int jj = (m + j) & 63;
            float p = Pk[jj];
            A = fmaf(p, uvb[0][jj], A);
            B = fmaf(p, uvb[1][jj], B);
            C = fmaf(p, uvb[2][jj], C);
        }
        g_alpha[j] = A;
        g_beta[j]  = B * LOG2E;
        sg[j] = C;
    }
    __syncthreads();
    if (j == 0) {
        float acc = Fcb[0];
        g_gam[0] = acc;
        #pragma unroll 1
        for (int k = 0; k < K; ++k) { acc += sg[k]; g_gam[k + 1] = acc; }
    }
}

// ============================================================
// Kernel B (fused, chunk-major): 128 thr = 2 rows x 2 warps/row.
// Buffer slot s at buf[(s&31)*67 + (s>>5) + 2]. x^2[n] at slot n,
// E[i] at slot i+16 (in-place safe: P2 batches descend in q).
// P3: lane c reads E at buf[CONST + c] -- zero ALU, conflict-free.
// ============================================================
__global__ void __launch_bounds__(128, 8) fused_kernel(const float* __restrict__ res,
                                                       float* __restrict__ out) {
    __shared__ float SM[2 * BUF + 4 * 32 * SSTR + 40];
    const int td   = threadIdx.x;
    const int lane = td & 31;
    const int wid  = td >> 5;
    const int h    = wid & 1;
    const int wr   = wid >> 1;
    const int b    = blockIdx.x * 2 + wr;
    float* buf  = SM + wr * BUF;
    float* stgw = SM + 2 * BUF + wid * (32 * SSTR);
    float* sal  = SM + 2 * BUF + 4 * 32 * SSTR;   // 12
    float* sgam = sal + K;                        // 13
    float* psum = sgam + (K + 1);                 // 4
    float* psq  = psum + 4;                       // 4
    const float* r = res + (size_t)b * Sn;
    float* orow = out + (size_t)b * Sn;

    // ---- P1: stage x^2 chunk-major + variance partials ----
    if (h == 0 && lane < 11) buf[(21 + lane) * NR + 1] = 0.f;  // x^2 slots -11..-1
    float sum = 0.f, sq = 0.f;
    #pragma unroll
    for (int m = 0; m < 8; ++m) {
        int f = h * 256 + lane + 32 * m;
        float4 q4 = reinterpret_cast<const float4*>(r)[f];
        float4 x2 = make_float4(q4.x * q4.x, q4.y * q4.y, q4.z * q4.z, q4.w * q4.w);
        int s0 = 4 * f;                            // rows s0..s0+3 (no wrap), same col
        int a = (s0 & 31) * NR + (s0 >> 5) + 2;
        buf[a] = x2.x; buf[a + NR] = x2.y; buf[a + 2 * NR] = x2.z; buf[a + 3 * NR] = x2.w;
        sum += (q4.x + q4.y) + (q4.z + q4.w);
        sq  += (x2.x + x2.y) + (x2.z + x2.w);
    }
    #pragma unroll
    for (int o = 16; o; o >>= 1) {
        sum += __shfl_xor_sync(FULLMASK, sum, o);
        sq  += __shfl_xor_sync(FULLMASK, sq, o);
    }
    if (lane == 0) { psum[wr * 2 + h] = sum; psq[wr * 2 + h] = sq; }

    // ---- coef results visible; P1 overlapped coef via PDL ----
    cudaGridDependencySynchronize();
    if (td < K)     sal[td]  = g_alpha[td];
    if (td < K + 1) sgam[td] = g_gam[td];
    __syncthreads();

    const float S = psum[wr * 2] + psum[wr * 2 + 1];
    const float Q = psq[wr * 2] + psq[wr * 2 + 1];
    const float sigma0 = (Q - S * S * (1.f / Sn)) * (1.f / (Sn - 1));

    // ---- P2: tap-major FIR, in-place, 8 descending q-batches ----
    // thread = (row r=lane, q-half g=h); outputs i = 32q + r, E slot i+16.
    int rbase[K];
    #pragma unroll
    for (int k = 0; k < K; ++k) {
        int rk = lane - k;
        rbase[k] = (rk & 31) * NR + 2 + ((rk < 0) ? -1 : 0);
    }
    int wb;
    { int rw = lane + 16; wb = (rw & 31) * NR + 2 + ((rw >= 32) ? 1 : 0); }

    #pragma unroll 1
    for (int bt = 7; bt >= 0; --bt) {
        const int qb = bt * 8 + h * 4;
        float acc[4] = {0.f, 0.f, 0.f, 0.f};
        #pragma unroll
        for (int k = 0; k < K; ++k) {
            const float a = sal[k];
            const float* p = buf + rbase[k] + qb;
            #pragma unroll
            for (int j = 0; j < 4; ++j) acc[j] = fmaf(a, p[j], acc[j]);
        }
        __syncthreads();                           // all reads before any write
        #pragma unroll
        for (int j = 0; j < 4; ++j) {
            int i = 32 * (qb + j) + lane;
            buf[wb + qb + j] = (acc[j] + sgam[min(i + 1, K)]) * LOG2E;
        }
        __syncthreads();
    }

    // ---- P3: chunk scans. c = h*32+lane, t0 = 32c-48, 5 tiles of 16 ----
    float beta[KS];
    #pragma unroll
    for (int k = 0; k < KS; ++k) beta[k] = g_beta[k];
    const int c  = h * 32 + lane;
    const int t0 = c * LCH - WUP;
    float hist[16];
    #pragma unroll
    for (int i = 0; i < 16; ++i) hist[i] = 0.f;
    float sigma = 0.f;

    #pragma unroll 1
    for (int tile = 0; tile < 5; ++tile) {
        const int sbase = tile * 16;
        #pragma unroll
        for (int ss = 0; ss < 16; ++ss) {
            const int t = t0 + sbase + ss;
            const int d = sbase + ss - 33;         // compile-time
            const int cst = (d & 31) * NR + (d >> 5) + 2;
            float e = buf[cst + c];                // E[t-1]: imm offset + lane base
            float p0 = 0.f, p1 = 0.f;
            #pragma unroll
            for (int k = 1; k < KS; k += 2) p0 = fmaf(beta[k], hist[(ss - 1 - k) & 15], p0);
            #pragma unroll
            for (int k = 2; k < KS; k += 2) p1 = fmaf(beta[k], hist[(ss - 1 - k) & 15], p1);
            float y = fmaf(beta[0], sigma, (p0 + p1) + e);
            float ex, lg;
            asm("ex2.approx.f32 %0, %1;" : "=f"(ex) : "f"(y));
            asm("lg2.approx.f32 %0, %1;" : "=f"(lg) : "f"(ex + 1.0f));
            float snew = fmaf(lg, LN2, 1e-6f);
            sigma = (t >= 1) ? snew : ((t == 0) ? sigma0 : 0.f);
            hist[ss] = sigma;                      // slot = t mod 16
            if (tile >= 3) stgw[lane * SSTR + ss] = sigma;
        }
        if (tile >= 3) {
            __syncwarp();
            const int T = (tile - 3) * 16;
            #pragma unroll
            for (int m = 0; m < 4; ++m) {
                int f = m * 32 + lane;
                int cc = f >> 2, q = f & 3;
                const float* sp = &stgw[cc * SSTR + 4 * q];
                *reinterpret_cast<float4*>(orow + (h * 32 + cc) * LCH + T + 4 * q) =
                    make_float4(sp[0], sp[1], sp[2], sp[3]);
            }
            __syncwarp();
        }
    }
}

extern "C" void kernel_launch(void* const* d_in, const int* in_sizes, int n_in,
                              void* d_out, int out_size) {
    (void)in_sizes; (void)n_in; (void)out_size;
    const float* res = (const float*)d_in[0];
    const float* Wih = (const float*)d_in[1];
    const float* Bih = (const float*)d_in[2];
    const float* Whh = (const float*)d_in[3];
    const float* Bhh = (const float*)d_in[4];
    const float* Fcw = (const float*)d_in[5];
    const float* Fcb = (const float*)d_in[6];
    float* out = (float*)d_out;

    coef_kernel<<<1, 64>>>(Wih, Bih, Whh, Bhh, Fcw, Fcb);

    cudaLaunchConfig_t cfg = {};
    cfg.gridDim  = dim3(Bn / 2);
    cfg.blockDim = dim3(128);
    cudaLaunchAttribute attr[1];
    attr[0].id = cudaLaunchAttributeProgrammaticStreamSerialization;
    attr[0].val.programmaticStreamSerializationAllowed = 1;
    cfg.attrs = attr;
    cfg.numAttrs = 1;
    cudaLaunchKernelEx(&cfg, fused_kernel, res, out);
}

// round 16
// speedup vs baseline: 1.1617x; 1.1617x over previous
#include <cuda_runtime.h>

#define FULLMASK 0xffffffffu
constexpr int Bn = 2048;
constexpr int Sn = 2048;
constexpr int K  = 16;     // taps for E-FIR / G prefix
constexpr int KS = 10;     // sigma-feedback taps in scan
constexpr int LCH = 32;    // stored steps per chunk (64 chunks/row)
constexpr int WUP = 48;    // warm-up steps (t0 = 32c-48)
constexpr int SSTR = 17;   // stage stride
constexpr float LOG2E = 1.4426950408889634f;
constexpr float LN2   = 0.6931471805599453f;
constexpr float EPOISON = -1e30f;   // softplus(-inf) -> 1e-6 ~ 0

__device__ float g_alpha[K];
__device__ float g_beta[K];                   // pre-scaled by LOG2E
__device__ float g_gam[K + 1];                // prefix sums incl fcb

// ============================================================
// Kernel A: coefficients (R14 version). Triggers PDL dependents at entry.
// ============================================================
__global__ void __launch_bounds__(64) coef_kernel(
        const float* __restrict__ Wih, const float* __restrict__ Bih,
        const float* __restrict__ Whh, const float* __restrict__ Bhh,
        const float* __restrict__ Fcw, const float* __restrict__ Fcb) {
    cudaTriggerProgrammaticLaunchCompletion();

    __shared__ __align__(16) float Ws[64 * 64];
    __shared__ __align__(16) float P[K][64];
    __shared__ __align__(16) float pbuf[2][64];
    __shared__ float uvb[3][64];
    __shared__ float sg[K];
    const int j = threadIdx.x;

    #pragma unroll
    for (int m = 0; m < 16; ++m)
        reinterpret_cast<float4*>(Ws)[j + 64 * m] =
            reinterpret_cast<const float4*>(Whh)[j + 64 * m];
    uvb[0][j] = Wih[2 * j];
    uvb[1][j] = Wih[2 * j + 1];
    uvb[2][j] = Bih[j] + Bhh[j];
    {
        float f = Fcw[j];
        P[0][j] = f;
        pbuf[0][j] = f;
    }
    __syncthreads();

    float Wc[64];
    #pragma unroll
    for (int r = 0; r < 64; ++r) Wc[r] = Ws[r * 64 + j];

    #pragma unroll 1
    for (int k = 1; k < K; ++k) {
        const float4* pp = reinterpret_cast<const float4*>(pbuf[(k - 1) & 1]);
        float a0 = 0.f, a1 = 0.f, a2 = 0.f, a3 = 0.f;
        #pragma unroll
        for (int m = 0; m < 16; ++m) {
            float4 q = pp[m];
            a0 = fmaf(Wc[4 * m + 0], q.x, a0);
            a1 = fmaf(Wc[4 * m + 1], q.y, a1);
            a2 = fmaf(Wc[4 * m + 2], q.z, a2);
            a3 = fmaf(Wc[4 * m + 3], q.w, a3);
        }
        float np = (a0 + a1) + (a2 + a3);
        pbuf[k & 1][j] = np;
        P[k][j] = np;
        __syncthreads();
    }

    if (j < K) {
        const float* Pk = P[j];
        float A = 0.f, B = 0.f, C = 0.f;
        #pragma unroll 8
        for (int m = 0; m < 64; ++m) {
            int jj = (m + j) & 63;
            float p = Pk[jj];
            A = fmaf(p, uvb[0][jj], A);
            B = fmaf(p, uvb[1][jj], B);
            C = fmaf(p, uvb[2][jj], C);
        }
        g_alpha[j] = A;
        g_beta[j]  = B * LOG2E;
        sg[j] = C;
    }
    __syncthreads();
    if (j == 0) {
        float acc = Fcb[0];
        g_gam[0] = acc;
        #pragma unroll 1
        for (int k = 0; k < K; ++k) { acc += sg[k]; g_gam[k + 1] = acc; }
    }
}

// ============================================================
// Kernel B (fused, in-place; R14 + zero-ALU P3):
//  P1: stage x^2 at xs[wr][16+n] + joint variance
//  -- cudaGridDependencySynchronize() --
//  P2: in-place FIR (two descending steps); E[i] at (i+52)+((i+52)>>5);
//      pads poisoned with -1e30 (softplus -> 1e-6 ~ 0 for t<1).
//  P3: 64 chunks; E addr = 33*c + const(s); single SEL only for t==0.
// ============================================================
__global__ void __launch_bounds__(128, 8) fused_kernel(const float* __restrict__ res,
                                                       float* __restrict__ out) {
    __shared__ __align__(16) float xs[2][2176];
    __shared__ float stg[4][32 * SSTR];
    __shared__ float sal[K];
    __shared__ float sgam[K + 1];
    __shared__ float psum[2][2], psq[2][2];
    const int td   = threadIdx.x;
    const int lane = td & 31;
    const int wid  = td >> 5;
    const int h    = wid & 1;
    const int wr   = wid >> 1;
    const int b    = blockIdx.x * 2 + wr;
    const float* r = res + (size_t)b * Sn;
    float* orow = out + (size_t)b * Sn;

    // ---- P1 ----
    if (lane < 16 && h == 0) xs[wr][lane] = 0.f;
    float sum = 0.f, sq = 0.f;
    #pragma unroll
    for (int m = 0; m < 8; ++m) {
        int f = h * 256 + lane + 32 * m;
        float4 q = reinterpret_cast<const float4*>(r)[f];
        float4 x2 = make_float4(q.x * q.x, q.y * q.y, q.z * q.z, q.w * q.w);
        *reinterpret_cast<float4*>(&xs[wr][16 + 4 * f]) = x2;
        sum += (q.x + q.y) + (q.z + q.w);
        sq  += (x2.x + x2.y) + (x2.z + x2.w);
    }
    #pragma unroll
    for (int o = 16; o; o >>= 1) {
        sum += __shfl_xor_sync(FULLMASK, sum, o);
        sq  += __shfl_xor_sync(FULLMASK, sq, o);
    }
    if (lane == 0) { psum[wr][h] = sum; psq[wr][h] = sq; }

    // ---- coef results become visible; P1 overlapped coef via PDL ----
    cudaGridDependencySynchronize();
    if (td < K)     sal[td]  = g_alpha[td];
    if (td < K + 1) sgam[td] = g_gam[td];
    __syncthreads();

    const float S = psum[wr][0] + psum[wr][1];
    const float Q = psq[wr][0] + psq[wr][1];
    const float sigma0 = (Q - S * S * (1.f / Sn)) * (1.f / (Sn - 1));
    float beta[KS];
    #pragma unroll
    for (int k = 0; k < KS; ++k) beta[k] = g_beta[k];

    // ---- P2: in-place FIR, two descending steps (R14 schedule) ----
    #pragma unroll 1
    for (int step = 0; step < 2; ++step) {
        const int B = (step == 0) ? (1536 - 512 * h) : (512 - 512 * h);
        const int i0 = B + lane * 16;
        float win[36];                       // win[u] = x^2[i0-16+u] = xs[i0+u]
        #pragma unroll
        for (int u = 0; u < 9; ++u)
            *reinterpret_cast<float4*>(&win[4 * u]) =
                *reinterpret_cast<const float4*>(&xs[wr][i0 + 4 * u]);
        __syncthreads();                     // all reads done before any write
        float acc[16];
        #pragma unroll
        for (int ii = 0; ii < 16; ++ii) acc[ii] = 0.f;
        #pragma unroll
        for (int k = 0; k < K; ++k) {
            float a = sal[k];
            #pragma unroll
            for (int ii = 0; ii < 16; ++ii)
                acc[ii] = fmaf(a, win[ii + 16 - k], acc[ii]);
        }
        #pragma unroll
        for (int ii = 0; ii < 16; ++ii) {
            int i = i0 + ii;
            float e = (acc[ii] + sgam[min(i + 1, K)]) * LOG2E;
            int j = i + 52;
            xs[wr][j + (j >> 5)] = e;
        }
        if (step == 1 && h == 0) {           // poison E pads [0,53): t<1 -> sigma ~ 0
            for (int z = lane; z < 53; z += 32) xs[wr][z] = EPOISON;
        }
        __syncthreads();
    }

    // ---- P3: chunk scans, fully unrolled. addr = 33c + const(s). ----
    float* stgw = stg[wid];
    const int c     = h * 32 + lane;
    const int ebase = 33 * c;                // lane base: addr = ebase + (3+s) + ((3+s)>>5)
    const int s_inj = 48 - 32 * c;           // step where t==0 (in range only for c=0,1)
    float hist[16];
    #pragma unroll
    for (int i = 0; i < 16; ++i) hist[i] = 0.f;
    float sigma = 0.f;

    auto flush = [&](int T) {
        __syncwarp();
        #pragma unroll
        for (int m = 0; m < 4; ++m) {
            int f = m * 32 + lane;
            int cc = f >> 2, q = f & 3;
            const float* sp = &stgw[cc * SSTR + 4 * q];
            *reinterpret_cast<float4*>(orow + (h * 32 + cc) * LCH + T + 4 * q) =
                make_float4(sp[0], sp[1], sp[2], sp[3]);
        }
        __syncwarp();
    };

    #pragma unroll
    for (int s = 0; s < 80; ++s) {
        const int qc = 3 + s;                             // compile-time
        float e = xs[wr][ebase + qc + (qc >> 5)];         // LDS [R+imm]
        float p0 = 0.f, p1 = 0.f, p2 = e;
        #pragma unroll
        for (int k = 1; k < KS; k += 3) p0 = fmaf(beta[k], hist[(s - 1 - k) & 15], p0);
        #pragma unroll
        for (int k = 2; k < KS; k += 3) p1 = fmaf(beta[k], hist[(s - 1 - k) & 15], p1);
        #pragma unroll
        for (int k = 3; k < KS; k += 3) p2 = fmaf(beta[k], hist[(s - 1 - k) & 15], p2);
        float y = fmaf(beta[0], sigma, (p0 + p1) + p2);   // y = x * log2(e)
        float ex, lg;
        asm("ex2.approx.f32 %0, %1;" : "=f"(ex) : "f"(y));
        asm("lg2.approx.f32 %0, %1;" : "=f"(lg) : "f"(ex + 1.0f));
        float snew = fmaf(lg, LN2, 1e-6f);                // softplus + EPS
        sigma = (s <= 48 && s == s_inj) ? sigma0 : snew;  // single SEL, only s<=48
        hist[s & 15] = sigma;                             // slot = t mod 16
        if (s >= 48) stgw[lane * SSTR + (s & 15)] = sigma;
        if (s == 63) flush(0);
        if (s == 79) flush(16);
    }
}

extern "C" void kernel_launch(void* const* d_in, const int* in_sizes, int n_in,
                              void* d_out, int out_size) {
    (void)in_sizes; (void)n_in; (void)out_size;
    const float* res = (const float*)d_in[0];
    const float* Wih = (const float*)d_in[1];
    const float* Bih = (const float*)d_in[2];
    const float* Whh = (const float*)d_in[3];
    const float* Bhh = (const float*)d_in[4];
    const float* Fcw = (const float*)d_in[5];
    const float* Fcb = (const float*)d_in[6];
    float* out = (float*)d_out;

    coef_kernel<<<1, 64>>>(Wih, Bih, Whh, Bhh, Fcw, Fcb);

    cudaLaunchConfig_t cfg = {};
    cfg.gridDim  = dim3(Bn / 2);
    cfg.blockDim = dim3(128);
    cudaLaunchAttribute attr[1];
    attr[0].id = cudaLaunchAttributeProgrammaticStreamSerialization;
    attr[0].val.programmaticStreamSerializationAllowed = 1;
    cfg.attrs = attr;
    cfg.numAttrs = 1;
    cudaLaunchKernelEx(&cfg, fused_kernel, res, out);
}